// round 3
// baseline (speedup 1.0000x reference)
#include <cuda_runtime.h>

// Dims: B=8, C=1024, T=512, HW=49, D=128, window=101, out_dim=128.

__device__ float g_part[8u * 4096u * 128u];  // [cc][b*T+t][d] partial GEMM (16.8 MB)
__device__ float g_y   [4096u * 128u];       // [B*T, 128] normalized projections (2 MB)

// ---------------------------------------------------------------------------
// Fused kernel: spatial-mean + projection GEMM partial.
// Block = (b, t-chunk of 64, c-chunk of 128). Per c in chunk:
//   A) stream 64*49 floats to smem (coalesced float4)
//   B) 64 threads reduce 49-sums -> smean[64]; 32 threads load pw[c,:] -> spw
//   C) all 256 threads: acc[4t][8d] += smean[t] * spw[d]
// Epilogue: write acc tile to g_part[cc].
// ---------------------------------------------------------------------------
__global__ void __launch_bounds__(256) k_fused(const float* __restrict__ in,
                                               const float* __restrict__ pw) {
    __shared__ __align__(16) float sdata[64 * 49];   // 12544 B
    __shared__ __align__(16) float smean[64];
    __shared__ __align__(16) float spw[128];

    int tid = threadIdx.x;
    int bx  = blockIdx.x;
    int cc  = bx & 7;
    int tch = (bx >> 3) & 7;
    int b   = bx >> 6;

    int tt = tid >> 4;        // 0..15 -> t0 = tt*4
    int td = tid & 15;        // 0..15 -> dA = td*4, dB = 64 + td*4
    int t0 = tt << 2;

    const float4* in4  = (const float4*)in;
    const float4* pw4  = (const float4*)pw;
    float4* spw4 = (float4*)spw;

    float4 acc[4][2];
    #pragma unroll
    for (int k = 0; k < 4; k++) {
        acc[k][0] = make_float4(0.f, 0.f, 0.f, 0.f);
        acc[k][1] = make_float4(0.f, 0.f, 0.f, 0.f);
    }

    for (int i = 0; i < 128; i++) {
        int c = (cc << 7) + i;
        // Phase A: load 64*49 = 3136 floats = 784 float4s (fully coalesced)
        size_t base4 = ((size_t)(b * 1024 + c) * 25088 + (size_t)tch * 3136) >> 2;
        for (int j = tid; j < 784; j += 256) {
            ((float4*)sdata)[j] = in4[base4 + j];
        }
        __syncthreads();

        // Phase B: 64 threads -> means; threads 64..95 -> pw row
        if (tid < 64) {
            const float* p = sdata + tid * 49;
            float s0 = 0.f, s1 = 0.f, s2 = 0.f, s3 = 0.f;
            #pragma unroll
            for (int j = 0; j < 48; j += 4) {
                s0 += p[j]; s1 += p[j + 1]; s2 += p[j + 2]; s3 += p[j + 3];
            }
            smean[tid] = ((s0 + s1) + (s2 + s3) + p[48]) * (1.0f / 49.0f);
        } else if (tid < 96) {
            int l = tid - 64;                       // 0..31
            spw4[l] = pw4[(size_t)c * 32 + l];
        }
        __syncthreads();

        // Phase C: outer-product FMA (next iter's Phase A overlaps this)
        float4 w0 = spw4[td];
        float4 w1 = spw4[16 + td];
        #pragma unroll
        for (int k = 0; k < 4; k++) {
            float m = smean[t0 + k];
            acc[k][0].x += m * w0.x; acc[k][0].y += m * w0.y;
            acc[k][0].z += m * w0.z; acc[k][0].w += m * w0.w;
            acc[k][1].x += m * w1.x; acc[k][1].y += m * w1.y;
            acc[k][1].z += m * w1.z; acc[k][1].w += m * w1.w;
        }
    }

    // Epilogue: acc -> g_part[cc][row][d]; coalesced (16 lanes cover 64 floats)
    int rowbase = b * 512 + tch * 64 + t0;
    float4* part4 = (float4*)g_part;
    #pragma unroll
    for (int k = 0; k < 4; k++) {
        size_t r = (size_t)cc * 4096 + rowbase + k;
        part4[r * 32 + td]      = acc[k][0];
        part4[r * 32 + 16 + td] = acc[k][1];
    }
}

// ---------------------------------------------------------------------------
// Epilogue: sum 8 partials + bias, L2 normalize, write g_y.
// One warp per row; lane owns one float4 (128 d = 32 lanes x 4).
// ---------------------------------------------------------------------------
__global__ void __launch_bounds__(256) k_norm(const float* __restrict__ pb) {
    int tid  = threadIdx.x;
    int lane = tid & 31;
    int row  = (blockIdx.x * 256 + tid) >> 5;    // 0..4095

    const float4* part4 = (const float4*)g_part;
    float4 v = make_float4(0.f, 0.f, 0.f, 0.f);
    #pragma unroll
    for (int cc = 0; cc < 8; cc++) {
        float4 p = part4[((size_t)cc * 4096 + row) * 32 + lane];
        v.x += p.x; v.y += p.y; v.z += p.z; v.w += p.w;
    }
    float4 bias = ((const float4*)pb)[lane];
    v.x += bias.x; v.y += bias.y; v.z += bias.z; v.w += bias.w;

    float ss = v.x * v.x + v.y * v.y + v.z * v.z + v.w * v.w;
    #pragma unroll
    for (int o = 16; o; o >>= 1) ss += __shfl_xor_sync(0xffffffffu, ss, o);
    float inv = 1.0f / fmaxf(sqrtf(ss), 1e-12f);
    v.x *= inv; v.y *= inv; v.z *= inv; v.w *= inv;
    ((float4*)g_y)[(size_t)row * 32 + lane] = v;
}

// ---------------------------------------------------------------------------
// Banded cosine-sim + fc + ReLU, fused. One warp per (b,t).
// ---------------------------------------------------------------------------
__global__ void __launch_bounds__(256) k_band_fc(const float* __restrict__ fw,
                                                 const float* __restrict__ fb,
                                                 float* __restrict__ out) {
    int tid  = threadIdx.x;
    int lane = tid & 31;
    int row  = (blockIdx.x * 256 + tid) >> 5;   // row = b*512 + t
    int t    = row & 511;

    const float4* y4  = (const float4*)g_y;
    const float4* fw4 = (const float4*)fw;
    float4 q   = y4[(size_t)row * 32 + lane];
    float4 acc = ((const float4*)fb)[lane];

    int w0 = (t < 50)  ? (50 - t)  : 0;
    int w1 = (562 - t < 101) ? (562 - t) : 101;

    for (int w = w0; w < w1; w++) {
        long long nrow = (long long)row + (w - 50);
        float4 kv = y4[nrow * 32 + lane];
        float p = q.x * kv.x + q.y * kv.y + q.z * kv.z + q.w * kv.w;
        #pragma unroll
        for (int o = 16; o; o >>= 1) p += __shfl_xor_sync(0xffffffffu, p, o);
        float4 fwv = fw4[w * 32 + lane];
        acc.x += p * fwv.x; acc.y += p * fwv.y; acc.z += p * fwv.z; acc.w += p * fwv.w;
    }

    acc.x = fmaxf(acc.x, 0.f);
    acc.y = fmaxf(acc.y, 0.f);
    acc.z = fmaxf(acc.z, 0.f);
    acc.w = fmaxf(acc.w, 0.f);
    ((float4*)out)[(size_t)row * 32 + lane] = acc;
}

// ---------------------------------------------------------------------------
extern "C" void kernel_launch(void* const* d_in, const int* in_sizes, int n_in,
                              void* d_out, int out_size) {
    const float* in = (const float*)d_in[0];   // [8,1024,512,7,7]
    const float* pw = (const float*)d_in[1];   // [1024,128]
    const float* pb = (const float*)d_in[2];   // [128]
    const float* fw = (const float*)d_in[3];   // [101,128]
    const float* fb = (const float*)d_in[4];   // [128]
    float* out = (float*)d_out;                // [8,512,128]

    k_fused<<<512, 256>>>(in, pw);             // mean + GEMM partials
    k_norm<<<512, 256>>>(pb);                  // 8-way sum + bias + L2 norm
    k_band_fc<<<512, 256>>>(fw, fb, out);      // banded sim + fc + ReLU
}

// round 4
// speedup vs baseline: 1.4541x; 1.4541x over previous
#include <cuda_runtime.h>

// Dims: B=8, C=1024, T=512, HW=49, D=128, window=101, out_dim=128.

__device__ float g_xm  [8u * 1024u * 512u];  // [B, C, T] spatial means (16.8 MB)
__device__ float g_part[2u * 4096u * 128u];  // [ksplit][b*T+t][d] GEMM partials (4 MB)
__device__ float g_y   [4096u * 128u];       // [B*T, 128] normalized projections (2 MB)

// ---------------------------------------------------------------------------
// Kernel 1: spatial mean over H*W=49 — streaming + smem transpose.
// Block = 128 consecutive flattened (b,c,t) rows = 25088 contiguous floats.
// Coalesced float4 loads into smem; 128 threads each sum 49 smem floats
// (stride 49 mod 32 = 17 -> conflict-free) and write 128 contiguous outputs.
// ---------------------------------------------------------------------------
__global__ void __launch_bounds__(256) k_mean(const float* __restrict__ in) {
    __shared__ __align__(16) float s[128 * 49];     // 25088 B
    const float4* in4 = (const float4*)in;
    float4* s4 = (float4*)s;
    size_t base4 = (size_t)blockIdx.x * 1568;       // 128*49/4 float4s per block

    #pragma unroll
    for (int i = 0; i < 6; i++) {
        int j = threadIdx.x + i * 256;
        s4[j] = in4[base4 + j];
    }
    {   // tail: 1568 = 6*256 + 32
        int j = threadIdx.x + 1536;
        if (j < 1568) s4[j] = in4[base4 + j];
    }
    __syncthreads();

    if (threadIdx.x < 128) {
        const float* p = s + threadIdx.x * 49;
        float acc = 0.f;
        #pragma unroll
        for (int i = 0; i < 49; i++) acc += p[i];
        g_xm[(size_t)blockIdx.x * 128 + threadIdx.x] = acc * (1.0f / 49.0f);
    }
}

// ---------------------------------------------------------------------------
// Kernel 2: projection GEMM, K-split by 2 -> partials.
// A = g_xm as A[m=(b,t)][k=c] at  b*524288 + k*512 + t  (K-major).
// Tile: 16 rows x 128 cols, BK=16, 256 threads, thread owns 2 rows x 4 cols.
// bx>>1 = tile index (256 tiles), bx&1 = K half. grid 512 ~ 3.5 blocks/SM.
// ---------------------------------------------------------------------------
__global__ void __launch_bounds__(256) k_proj(const float* __restrict__ pw) {
    __shared__ __align__(16) float As[16][16];
    __shared__ __align__(16) float Bs[16][128];

    int tid = threadIdx.x;
    int tx  = tid & 31;
    int ty  = tid >> 5;
    int bx  = blockIdx.x;
    int z   = bx & 1;                   // K half
    int m0  = (bx >> 1) * 16;           // row tile start
    int b   = m0 >> 9;
    int t0  = m0 & 511;
    const float* Abase = g_xm + (size_t)b * 524288 + t0;
    const float4* pw4 = (const float4*)pw;

    int akk = tid >> 4;                 // 0..15 (k within tile)
    int amm = tid & 15;                 // 0..15 (m within tile)

    float4 acc[2];
    acc[0] = acc[1] = make_float4(0.f, 0.f, 0.f, 0.f);

    int kbeg = z * 512, kend = kbeg + 512;
    for (int k0 = kbeg; k0 < kend; k0 += 16) {
        As[akk][amm] = Abase[(size_t)(k0 + akk) * 512 + amm];
        {
            int i0 = tid, i1 = tid + 256;
            ((float4*)Bs)[i0] = pw4[(size_t)(k0 + (i0 >> 5)) * 32 + (i0 & 31)];
            ((float4*)Bs)[i1] = pw4[(size_t)(k0 + (i1 >> 5)) * 32 + (i1 & 31)];
        }
        __syncthreads();

        #pragma unroll
        for (int k = 0; k < 16; k++) {
            float a0 = As[k][ty * 2 + 0];
            float a1 = As[k][ty * 2 + 1];
            float4 bb = ((const float4*)Bs[k])[tx];
            acc[0].x += a0 * bb.x; acc[0].y += a0 * bb.y; acc[0].z += a0 * bb.z; acc[0].w += a0 * bb.w;
            acc[1].x += a1 * bb.x; acc[1].y += a1 * bb.y; acc[1].z += a1 * bb.z; acc[1].w += a1 * bb.w;
        }
        __syncthreads();
    }

    #pragma unroll
    for (int rr = 0; rr < 2; rr++) {
        size_t row = (size_t)(m0 + ty * 2 + rr);
        ((float4*)g_part)[((size_t)z * 4096 + row) * 32 + tx] = acc[rr];
    }
}

// ---------------------------------------------------------------------------
// Epilogue: sum 2 partials + bias, L2 normalize, write g_y.
// One warp per row; lane owns one float4 (128 d = 32 lanes x 4).
// ---------------------------------------------------------------------------
__global__ void __launch_bounds__(256) k_norm(const float* __restrict__ pb) {
    int tid  = threadIdx.x;
    int lane = tid & 31;
    int row  = (blockIdx.x * 256 + tid) >> 5;    // 0..4095

    const float4* part4 = (const float4*)g_part;
    float4 p0 = part4[(size_t)row * 32 + lane];
    float4 p1 = part4[((size_t)4096 + row) * 32 + lane];
    float4 bias = ((const float4*)pb)[lane];
    float4 v;
    v.x = p0.x + p1.x + bias.x;
    v.y = p0.y + p1.y + bias.y;
    v.z = p0.z + p1.z + bias.z;
    v.w = p0.w + p1.w + bias.w;

    float ss = v.x * v.x + v.y * v.y + v.z * v.z + v.w * v.w;
    #pragma unroll
    for (int o = 16; o; o >>= 1) ss += __shfl_xor_sync(0xffffffffu, ss, o);
    float inv = 1.0f / fmaxf(sqrtf(ss), 1e-12f);
    v.x *= inv; v.y *= inv; v.z *= inv; v.w *= inv;
    ((float4*)g_y)[(size_t)row * 32 + lane] = v;
}

// ---------------------------------------------------------------------------
// Banded cosine-sim + fc + ReLU, fused. One warp per (b,t).
// ---------------------------------------------------------------------------
__global__ void __launch_bounds__(256) k_band_fc(const float* __restrict__ fw,
                                                 const float* __restrict__ fb,
                                                 float* __restrict__ out) {
    int tid  = threadIdx.x;
    int lane = tid & 31;
    int row  = (blockIdx.x * 256 + tid) >> 5;   // row = b*512 + t
    int t    = row & 511;

    const float4* y4  = (const float4*)g_y;
    const float4* fw4 = (const float4*)fw;
    float4 q   = y4[(size_t)row * 32 + lane];
    float4 acc = ((const float4*)fb)[lane];

    int w0 = (t < 50)  ? (50 - t)  : 0;
    int w1 = (562 - t < 101) ? (562 - t) : 101;

    for (int w = w0; w < w1; w++) {
        long long nrow = (long long)row + (w - 50);
        float4 kv = y4[nrow * 32 + lane];
        float p = q.x * kv.x + q.y * kv.y + q.z * kv.z + q.w * kv.w;
        #pragma unroll
        for (int o = 16; o; o >>= 1) p += __shfl_xor_sync(0xffffffffu, p, o);
        float4 fwv = fw4[w * 32 + lane];
        acc.x += p * fwv.x; acc.y += p * fwv.y; acc.z += p * fwv.z; acc.w += p * fwv.w;
    }

    acc.x = fmaxf(acc.x, 0.f);
    acc.y = fmaxf(acc.y, 0.f);
    acc.z = fmaxf(acc.z, 0.f);
    acc.w = fmaxf(acc.w, 0.f);
    ((float4*)out)[(size_t)row * 32 + lane] = acc;
}

// ---------------------------------------------------------------------------
extern "C" void kernel_launch(void* const* d_in, const int* in_sizes, int n_in,
                              void* d_out, int out_size) {
    const float* in = (const float*)d_in[0];   // [8,1024,512,7,7]
    const float* pw = (const float*)d_in[1];   // [1024,128]
    const float* pb = (const float*)d_in[2];   // [128]
    const float* fw = (const float*)d_in[3];   // [101,128]
    const float* fb = (const float*)d_in[4];   // [128]
    float* out = (float*)d_out;                // [8,512,128]

    k_mean<<<32768, 256>>>(in);                // block = 128 (b,c,t) rows
    k_proj<<<512, 256>>>(pw);                  // 256 tiles x 2 K-halves
    k_norm<<<512, 256>>>(pb);                  // partial sum + bias + L2 norm
    k_band_fc<<<512, 256>>>(fw, fb, out);      // banded sim + fc + ReLU
}

// round 6
// speedup vs baseline: 1.6800x; 1.1553x over previous
#include <cuda_runtime.h>
#include <cstdint>

// Dims: B=8, C=1024, T=512, HW=49, D=128, window=101, out_dim=128.

__device__ float g_xm  [8u * 1024u * 512u];  // [B, C, T] spatial means (16.8 MB)
__device__ float g_part[4u * 4096u * 128u];  // [ksplit][b*T+t][d] GEMM partials (8 MB)
__device__ float g_y   [4096u * 128u];       // [B*T, 128] normalized projections (2 MB)

#define CP_ASYNC16(dst_u32, src_ptr) \
    asm volatile("cp.async.cg.shared.global [%0], [%1], 16;\n" \
                 :: "r"(dst_u32), "l"(src_ptr))
#define CP_ASYNC_WAIT_ALL() \
    asm volatile("cp.async.commit_group;\ncp.async.wait_group 0;\n" ::: "memory")

// ---------------------------------------------------------------------------
// Kernel 1: spatial mean over 49 — streaming via cp.async + smem reduce.
// Block = 128 consecutive flattened (b,c,t) rows = 25088 contiguous floats.
// Stride-49 smem reads are conflict-free (gcd(49,32)=1).
// ---------------------------------------------------------------------------
__global__ void __launch_bounds__(256) k_mean(const float* __restrict__ in) {
    __shared__ __align__(16) float s[128 * 49];     // 25088 B
    unsigned int sbase = (unsigned int)__cvta_generic_to_shared(s);
    const float4* src = (const float4*)in + (size_t)blockIdx.x * 1568;

    #pragma unroll
    for (int i = 0; i < 6; i++) {
        int j = threadIdx.x + i * 256;
        CP_ASYNC16(sbase + j * 16, src + j);
    }
    {   // tail: 1568 = 6*256 + 32
        int j = threadIdx.x + 1536;
        if (j < 1568) CP_ASYNC16(sbase + j * 16, src + j);
    }
    CP_ASYNC_WAIT_ALL();
    __syncthreads();

    if (threadIdx.x < 128) {
        const float* p = s + threadIdx.x * 49;
        float s0 = 0.f, s1 = 0.f, s2 = 0.f, s3 = 0.f;
        #pragma unroll
        for (int j = 0; j < 48; j += 4) {
            s0 += p[j]; s1 += p[j + 1]; s2 += p[j + 2]; s3 += p[j + 3];
        }
        float acc = (s0 + s1) + (s2 + s3) + p[48];
        g_xm[(size_t)blockIdx.x * 128 + threadIdx.x] = acc * (1.0f / 49.0f);
    }
}

// ---------------------------------------------------------------------------
// Kernel 2: projection GEMM, K-split by 4 -> partials.
// A = g_xm as A[m=(b,t)][k=c] at  b*524288 + k*512 + t  (K-major).
// Tile: 16 rows x 128 cols, BK=16, 256 threads, thread owns 2 rows x 4 cols.
// bx>>2 = tile (256 tiles), bx&3 = K quarter. grid 1024 ~ 7 blocks/SM.
// ---------------------------------------------------------------------------
__global__ void __launch_bounds__(256) k_proj(const float* __restrict__ pw) {
    __shared__ __align__(16) float As[16][16];
    __shared__ __align__(16) float Bs[16][128];

    int tid = threadIdx.x;
    int tx  = tid & 31;
    int ty  = tid >> 5;
    int bx  = blockIdx.x;
    int z   = bx & 3;                   // K quarter
    int m0  = (bx >> 2) * 16;           // row tile start
    int b   = m0 >> 9;
    int t0  = m0 & 511;
    const float* Abase = g_xm + (size_t)b * 524288 + t0;
    const float4* pw4 = (const float4*)pw;

    int akk = tid >> 4;                 // 0..15 (k within tile)
    int amm = tid & 15;                 // 0..15 (m within tile)

    float4 acc[2];
    acc[0] = acc[1] = make_float4(0.f, 0.f, 0.f, 0.f);

    int kbeg = z * 256, kend = kbeg + 256;
    for (int k0 = kbeg; k0 < kend; k0 += 16) {
        As[akk][amm] = Abase[(size_t)(k0 + akk) * 512 + amm];
        {
            int i0 = tid, i1 = tid + 256;
            ((float4*)Bs)[i0] = pw4[(size_t)(k0 + (i0 >> 5)) * 32 + (i0 & 31)];
            ((float4*)Bs)[i1] = pw4[(size_t)(k0 + (i1 >> 5)) * 32 + (i1 & 31)];
        }
        __syncthreads();

        #pragma unroll
        for (int k = 0; k < 16; k++) {
            float a0 = As[k][ty * 2 + 0];
            float a1 = As[k][ty * 2 + 1];
            float4 bb = ((const float4*)Bs[k])[tx];
            acc[0].x += a0 * bb.x; acc[0].y += a0 * bb.y; acc[0].z += a0 * bb.z; acc[0].w += a0 * bb.w;
            acc[1].x += a1 * bb.x; acc[1].y += a1 * bb.y; acc[1].z += a1 * bb.z; acc[1].w += a1 * bb.w;
        }
        __syncthreads();
    }

    #pragma unroll
    for (int rr = 0; rr < 2; rr++) {
        size_t row = (size_t)(m0 + ty * 2 + rr);
        ((float4*)g_part)[((size_t)z * 4096 + row) * 32 + tx] = acc[rr];
    }
}

// ---------------------------------------------------------------------------
// Epilogue: sum 4 partials + bias, L2 normalize, write g_y.
// ---------------------------------------------------------------------------
__global__ void __launch_bounds__(256) k_norm(const float* __restrict__ pb) {
    int tid  = threadIdx.x;
    int lane = tid & 31;
    int row  = (blockIdx.x * 256 + tid) >> 5;    // 0..4095

    const float4* part4 = (const float4*)g_part;
    float4 v = ((const float4*)pb)[lane];
    #pragma unroll
    for (int z = 0; z < 4; z++) {
        float4 p = part4[((size_t)z * 4096 + row) * 32 + lane];
        v.x += p.x; v.y += p.y; v.z += p.z; v.w += p.w;
    }

    float ss = v.x * v.x + v.y * v.y + v.z * v.z + v.w * v.w;
    #pragma unroll
    for (int o = 16; o; o >>= 1) ss += __shfl_xor_sync(0xffffffffu, ss, o);
    float inv = 1.0f / fmaxf(sqrtf(ss), 1e-12f);
    v.x *= inv; v.y *= inv; v.z *= inv; v.w *= inv;
    ((float4*)g_y)[(size_t)row * 32 + lane] = v;
}

// ---------------------------------------------------------------------------
// Banded cosine-sim + fc + ReLU, fused.
// TWO warps per (b,t): warp half 0 covers w in [w0,50), half 1 covers
// [50,w1). fc is linear in the dots so partial accs add. 4-way interleaved
// w-loop pipelines 4 independent shfl-reduction chains. Combine via smem.
// Block = 256 threads = 8 warps = 4 t's; grid = 1024.
// ---------------------------------------------------------------------------
__global__ void __launch_bounds__(256) k_band_fc(const float* __restrict__ fw,
                                                 const float* __restrict__ fb,
                                                 float* __restrict__ out) {
    __shared__ __align__(16) float4 sacc[8][32];

    int tid  = threadIdx.x;
    int lane = tid & 31;
    int wrp  = tid >> 5;                 // 0..7
    int half = wrp & 1;
    int row  = blockIdx.x * 4 + (wrp >> 1);   // row = b*512 + t
    int t    = row & 511;

    const float4* y4  = (const float4*)g_y;
    const float4* fw4 = (const float4*)fw;
    float4 q   = y4[(size_t)row * 32 + lane];
    float4 acc = make_float4(0.f, 0.f, 0.f, 0.f);

    int w0 = (t < 50)  ? (50 - t)  : 0;
    int w1 = (562 - t < 101) ? (562 - t) : 101;
    int wa = half ? 50 : w0;
    int wb = half ? w1 : 50;

    int w = wa;
    for (; w + 3 < wb; w += 4) {
        int nr = row + (w - 50);
        float4 k0 = y4[(size_t)(nr + 0) * 32 + lane];
        float4 k1 = y4[(size_t)(nr + 1) * 32 + lane];
        float4 k2 = y4[(size_t)(nr + 2) * 32 + lane];
        float4 k3 = y4[(size_t)(nr + 3) * 32 + lane];
        float p0 = q.x * k0.x + q.y * k0.y + q.z * k0.z + q.w * k0.w;
        float p1 = q.x * k1.x + q.y * k1.y + q.z * k1.z + q.w * k1.w;
        float p2 = q.x * k2.x + q.y * k2.y + q.z * k2.z + q.w * k2.w;
        float p3 = q.x * k3.x + q.y * k3.y + q.z * k3.z + q.w * k3.w;
        #pragma unroll
        for (int o = 16; o; o >>= 1) {
            p0 += __shfl_xor_sync(0xffffffffu, p0, o);
            p1 += __shfl_xor_sync(0xffffffffu, p1, o);
            p2 += __shfl_xor_sync(0xffffffffu, p2, o);
            p3 += __shfl_xor_sync(0xffffffffu, p3, o);
        }
        float4 f0 = fw4[(w + 0) * 32 + lane];
        float4 f1 = fw4[(w + 1) * 32 + lane];
        float4 f2 = fw4[(w + 2) * 32 + lane];
        float4 f3 = fw4[(w + 3) * 32 + lane];
        acc.x += p0 * f0.x + p1 * f1.x + p2 * f2.x + p3 * f3.x;
        acc.y += p0 * f0.y + p1 * f1.y + p2 * f2.y + p3 * f3.y;
        acc.z += p0 * f0.z + p1 * f1.z + p2 * f2.z + p3 * f3.z;
        acc.w += p0 * f0.w + p1 * f1.w + p2 * f2.w + p3 * f3.w;
    }
    for (; w < wb; w++) {
        int nr = row + (w - 50);
        float4 kv = y4[(size_t)nr * 32 + lane];
        float p = q.x * kv.x + q.y * kv.y + q.z * kv.z + q.w * kv.w;
        #pragma unroll
        for (int o = 16; o; o >>= 1) p += __shfl_xor_sync(0xffffffffu, p, o);
        float4 fv = fw4[w * 32 + lane];
        acc.x += p * fv.x; acc.y += p * fv.y; acc.z += p * fv.z; acc.w += p * fv.w;
    }

    sacc[wrp][lane] = acc;
    __syncthreads();

    if (wrp < 4) {
        float4 a = sacc[wrp * 2][lane];
        float4 bpart = sacc[wrp * 2 + 1][lane];
        float4 bias = ((const float4*)fb)[lane];
        float4 v;
        v.x = fmaxf(a.x + bpart.x + bias.x, 0.f);
        v.y = fmaxf(a.y + bpart.y + bias.y, 0.f);
        v.z = fmaxf(a.z + bpart.z + bias.z, 0.f);
        v.w = fmaxf(a.w + bpart.w + bias.w, 0.f);
        int orow = blockIdx.x * 4 + wrp;
        ((float4*)out)[(size_t)orow * 32 + lane] = v;
    }
}

// ---------------------------------------------------------------------------
extern "C" void kernel_launch(void* const* d_in, const int* in_sizes, int n_in,
                              void* d_out, int out_size) {
    const float* in = (const float*)d_in[0];   // [8,1024,512,7,7]
    const float* pw = (const float*)d_in[1];   // [1024,128]
    const float* pb = (const float*)d_in[2];   // [128]
    const float* fw = (const float*)d_in[3];   // [101,128]
    const float* fb = (const float*)d_in[4];   // [128]
    float* out = (float*)d_out;                // [8,512,128]

    k_mean<<<32768, 256>>>(in);                // block = 128 (b,c,t) rows
    k_proj<<<1024, 256>>>(pw);                 // 256 tiles x 4 K-quarters
    k_norm<<<512, 256>>>(pb);                  // partial sum + bias + L2 norm
    k_band_fc<<<1024, 256>>>(fw, fb, out);     // 2 warps per (b,t)
}

// round 7
// speedup vs baseline: 1.6942x; 1.0084x over previous
#include <cuda_runtime.h>
#include <cstdint>

// Dims: B=8, C=1024, T=512, HW=49, D=128, window=101, out_dim=128.

__device__ float g_xm  [8u * 1024u * 512u];  // [B, C, T] spatial means (16.8 MB)
__device__ float g_part[8u * 4096u * 128u];  // [ksplit][b*T+t][d] GEMM partials (16.8 MB)
__device__ float g_y   [4096u * 128u];       // [B*T, 128] normalized projections (2 MB)

#define CP_ASYNC16(dst_u32, src_ptr) \
    asm volatile("cp.async.cg.shared.global [%0], [%1], 16;\n" \
                 :: "r"(dst_u32), "l"(src_ptr))
#define CP_ASYNC_WAIT_ALL() \
    asm volatile("cp.async.commit_group;\ncp.async.wait_group 0;\n" ::: "memory")

// Packed fp32x2 FMA (sm_100+): d = a*b + d per 32-bit half. FFMA2 in SASS.
__device__ __forceinline__ void fma2(unsigned long long& d,
                                     unsigned long long a,
                                     unsigned long long b) {
    asm("fma.rn.f32x2 %0, %1, %2, %0;" : "+l"(d) : "l"(a), "l"(b));
}
__device__ __forceinline__ unsigned long long bcast2(float x) {
    unsigned long long r;
    unsigned int u = __float_as_uint(x);
    asm("mov.b64 %0, {%1, %1};" : "=l"(r) : "r"(u));
    return r;
}
__device__ __forceinline__ float lo32(unsigned long long v) {
    return __uint_as_float((unsigned int)(v & 0xffffffffull));
}
__device__ __forceinline__ float hi32(unsigned long long v) {
    return __uint_as_float((unsigned int)(v >> 32));
}

// ---------------------------------------------------------------------------
// Kernel 1: spatial mean over 49 — streaming via cp.async + smem reduce.
// Block = 128 consecutive flattened (b,c,t) rows = 25088 contiguous floats.
// Stride-49 smem reads are conflict-free (gcd(49,32)=1).
// ---------------------------------------------------------------------------
__global__ void __launch_bounds__(256) k_mean(const float* __restrict__ in) {
    __shared__ __align__(16) float s[128 * 49];     // 25088 B
    unsigned int sbase = (unsigned int)__cvta_generic_to_shared(s);
    const float4* src = (const float4*)in + (size_t)blockIdx.x * 1568;

    #pragma unroll
    for (int i = 0; i < 6; i++) {
        int j = threadIdx.x + i * 256;
        CP_ASYNC16(sbase + j * 16, src + j);
    }
    {   // tail: 1568 = 6*256 + 32
        int j = threadIdx.x + 1536;
        if (j < 1568) CP_ASYNC16(sbase + j * 16, src + j);
    }
    CP_ASYNC_WAIT_ALL();
    __syncthreads();

    if (threadIdx.x < 128) {
        const float* p = s + threadIdx.x * 49;
        float s0 = 0.f, s1 = 0.f, s2 = 0.f, s3 = 0.f;
        #pragma unroll
        for (int j = 0; j < 48; j += 4) {
            s0 += p[j]; s1 += p[j + 1]; s2 += p[j + 2]; s3 += p[j + 3];
        }
        float acc = (s0 + s1) + (s2 + s3) + p[48];
        g_xm[(size_t)blockIdx.x * 128 + threadIdx.x] = acc * (1.0f / 49.0f);
    }
}

// ---------------------------------------------------------------------------
// Kernel 2: projection GEMM, K-split by 8 -> partials, packed f32x2 FMA.
// A = g_xm as A[m=(b,t)][k=c] at  b*524288 + k*512 + t  (K-major).
// Tile: 16 rows x 128 cols, BK=16, 256 threads, thread owns 2 rows x 4 cols
// (held as 2x2 packed f32x2 accumulators -> FFMA2, 2x fp32 throughput).
// bx>>3 = tile (256 tiles), bx&7 = K eighth. grid 2048 ~ 8 blocks/SM.
// ---------------------------------------------------------------------------
__global__ void __launch_bounds__(256) k_proj(const float* __restrict__ pw) {
    __shared__ __align__(16) float As[16][16];
    __shared__ __align__(16) float Bs[16][128];

    int tid = threadIdx.x;
    int tx  = tid & 31;
    int ty  = tid >> 5;
    int bx  = blockIdx.x;
    int z   = bx & 7;                   // K eighth
    int m0  = (bx >> 3) * 16;           // row tile start
    int b   = m0 >> 9;
    int t0  = m0 & 511;
    const float* Abase = g_xm + (size_t)b * 524288 + t0;
    const float4* pw4 = (const float4*)pw;

    int akk = tid >> 4;                 // 0..15 (k within tile)
    int amm = tid & 15;                 // 0..15 (m within tile)

    unsigned long long acc00 = 0ull, acc01 = 0ull;   // row0: d lo-pair, hi-pair
    unsigned long long acc10 = 0ull, acc11 = 0ull;   // row1

    int kbeg = z * 128, kend = kbeg + 128;
    for (int k0 = kbeg; k0 < kend; k0 += 16) {
        As[akk][amm] = Abase[(size_t)(k0 + akk) * 512 + amm];
        {
            int i0 = tid, i1 = tid + 256;
            ((float4*)Bs)[i0] = pw4[(size_t)(k0 + (i0 >> 5)) * 32 + (i0 & 31)];
            ((float4*)Bs)[i1] = pw4[(size_t)(k0 + (i1 >> 5)) * 32 + (i1 & 31)];
        }
        __syncthreads();

        #pragma unroll
        for (int k = 0; k < 16; k++) {
            unsigned long long a0 = bcast2(As[k][ty * 2 + 0]);
            unsigned long long a1 = bcast2(As[k][ty * 2 + 1]);
            const ulonglong2* brow = (const ulonglong2*)Bs[k];
            ulonglong2 bb = brow[tx];           // one LDS.128: 4 floats
            fma2(acc00, a0, bb.x);
            fma2(acc01, a0, bb.y);
            fma2(acc10, a1, bb.x);
            fma2(acc11, a1, bb.y);
        }
        __syncthreads();
    }

    float4 v0 = make_float4(lo32(acc00), hi32(acc00), lo32(acc01), hi32(acc01));
    float4 v1 = make_float4(lo32(acc10), hi32(acc10), lo32(acc11), hi32(acc11));
    size_t row0 = (size_t)(m0 + ty * 2);
    ((float4*)g_part)[((size_t)z * 4096 + row0)     * 32 + tx] = v0;
    ((float4*)g_part)[((size_t)z * 4096 + row0 + 1) * 32 + tx] = v1;
}

// ---------------------------------------------------------------------------
// Epilogue: sum 8 partials + bias, L2 normalize, write g_y.
// ---------------------------------------------------------------------------
__global__ void __launch_bounds__(256) k_norm(const float* __restrict__ pb) {
    int tid  = threadIdx.x;
    int lane = tid & 31;
    int row  = (blockIdx.x * 256 + tid) >> 5;    // 0..4095

    const float4* part4 = (const float4*)g_part;
    float4 v = ((const float4*)pb)[lane];
    #pragma unroll
    for (int z = 0; z < 8; z++) {
        float4 p = part4[((size_t)z * 4096 + row) * 32 + lane];
        v.x += p.x; v.y += p.y; v.z += p.z; v.w += p.w;
    }

    float ss = v.x * v.x + v.y * v.y + v.z * v.z + v.w * v.w;
    #pragma unroll
    for (int o = 16; o; o >>= 1) ss += __shfl_xor_sync(0xffffffffu, ss, o);
    float inv = 1.0f / fmaxf(sqrtf(ss), 1e-12f);
    v.x *= inv; v.y *= inv; v.z *= inv; v.w *= inv;
    ((float4*)g_y)[(size_t)row * 32 + lane] = v;
}

// ---------------------------------------------------------------------------
// Banded cosine-sim + fc + ReLU, fused.
// FOUR warps per (b,t): quarter q covers w in [qlo,qhi) ∩ [w0,w1).
// fc is linear in the dots so partial accs add. 4-way interleaved w-loop
// pipelines 4 independent shfl chains. Block = 8 warps = 2 t's; grid = 2048.
// ---------------------------------------------------------------------------
__global__ void __launch_bounds__(256) k_band_fc(const float* __restrict__ fw,
                                                 const float* __restrict__ fb,
                                                 float* __restrict__ out) {
    __shared__ __align__(16) float4 sacc[8][32];

    int tid  = threadIdx.x;
    int lane = tid & 31;
    int wrp  = tid >> 5;                 // 0..7
    int quar = wrp & 3;
    int row  = blockIdx.x * 2 + (wrp >> 2);   // row = b*512 + t
    int t    = row & 511;

    const float4* y4  = (const float4*)g_y;
    const float4* fw4 = (const float4*)fw;
    float4 q   = y4[(size_t)row * 32 + lane];
    float4 acc = make_float4(0.f, 0.f, 0.f, 0.f);

    int w0 = (t < 50)  ? (50 - t)  : 0;
    int w1 = (562 - t < 101) ? (562 - t) : 101;
    const int qlo_t[4] = {0, 26, 51, 76};
    const int qhi_t[4] = {26, 51, 76, 101};
    int wa = w0 > qlo_t[quar] ? w0 : qlo_t[quar];
    int wb = w1 < qhi_t[quar] ? w1 : qhi_t[quar];

    int w = wa;
    for (; w + 3 < wb; w += 4) {
        int nr = row + (w - 50);
        float4 k0 = y4[(size_t)(nr + 0) * 32 + lane];
        float4 k1 = y4[(size_t)(nr + 1) * 32 + lane];
        float4 k2 = y4[(size_t)(nr + 2) * 32 + lane];
        float4 k3 = y4[(size_t)(nr + 3) * 32 + lane];
        float p0 = q.x * k0.x + q.y * k0.y + q.z * k0.z + q.w * k0.w;
        float p1 = q.x * k1.x + q.y * k1.y + q.z * k1.z + q.w * k1.w;
        float p2 = q.x * k2.x + q.y * k2.y + q.z * k2.z + q.w * k2.w;
        float p3 = q.x * k3.x + q.y * k3.y + q.z * k3.z + q.w * k3.w;
        #pragma unroll
        for (int o = 16; o; o >>= 1) {
            p0 += __shfl_xor_sync(0xffffffffu, p0, o);
            p1 += __shfl_xor_sync(0xffffffffu, p1, o);
            p2 += __shfl_xor_sync(0xffffffffu, p2, o);
            p3 += __shfl_xor_sync(0xffffffffu, p3, o);
        }
        float4 f0 = fw4[(w + 0) * 32 + lane];
        float4 f1 = fw4[(w + 1) * 32 + lane];
        float4 f2 = fw4[(w + 2) * 32 + lane];
        float4 f3 = fw4[(w + 3) * 32 + lane];
        acc.x += p0 * f0.x + p1 * f1.x + p2 * f2.x + p3 * f3.x;
        acc.y += p0 * f0.y + p1 * f1.y + p2 * f2.y + p3 * f3.y;
        acc.z += p0 * f0.z + p1 * f1.z + p2 * f2.z + p3 * f3.z;
        acc.w += p0 * f0.w + p1 * f1.w + p2 * f2.w + p3 * f3.w;
    }
    for (; w < wb; w++) {
        int nr = row + (w - 50);
        float4 kv = y4[(size_t)nr * 32 + lane];
        float p = q.x * kv.x + q.y * kv.y + q.z * kv.z + q.w * kv.w;
        #pragma unroll
        for (int o = 16; o; o >>= 1) p += __shfl_xor_sync(0xffffffffu, p, o);
        float4 fv = fw4[w * 32 + lane];
        acc.x += p * fv.x; acc.y += p * fv.y; acc.z += p * fv.z; acc.w += p * fv.w;
    }

    sacc[wrp][lane] = acc;
    __syncthreads();

    if (wrp < 2) {
        float4 a0 = sacc[wrp * 4 + 0][lane];
        float4 a1 = sacc[wrp * 4 + 1][lane];
        float4 a2 = sacc[wrp * 4 + 2][lane];
        float4 a3 = sacc[wrp * 4 + 3][lane];
        float4 bias = ((const float4*)fb)[lane];
        float4 v;
        v.x = fmaxf((a0.x + a1.x) + (a2.x + a3.x) + bias.x, 0.f);
        v.y = fmaxf((a0.y + a1.y) + (a2.y + a3.y) + bias.y, 0.f);
        v.z = fmaxf((a0.z + a1.z) + (a2.z + a3.z) + bias.z, 0.f);
        v.w = fmaxf((a0.w + a1.w) + (a2.w + a3.w) + bias.w, 0.f);
        int orow = blockIdx.x * 2 + wrp;
        ((float4*)out)[(size_t)orow * 32 + lane] = v;
    }
}

// ---------------------------------------------------------------------------
extern "C" void kernel_launch(void* const* d_in, const int* in_sizes, int n_in,
                              void* d_out, int out_size) {
    const float* in = (const float*)d_in[0];   // [8,1024,512,7,7]
    const float* pw = (const float*)d_in[1];   // [1024,128]
    const float* pb = (const float*)d_in[2];   // [128]
    const float* fw = (const float*)d_in[3];   // [101,128]
    const float* fb = (const float*)d_in[4];   // [128]
    float* out = (float*)d_out;                // [8,512,128]

    k_mean<<<32768, 256>>>(in);                // block = 128 (b,c,t) rows
    k_proj<<<2048, 256>>>(pw);                 // 256 tiles x 8 K-eighths
    k_norm<<<512, 256>>>(pb);                  // partial sum + bias + L2 norm
    k_band_fc<<<2048, 256>>>(fw, fb, out);     // 4 warps per (b,t)
}

// round 9
// speedup vs baseline: 1.7100x; 1.0093x over previous
#include <cuda_runtime.h>
#include <cstdint>

// Dims: B=8, C=1024, T=512, HW=49, D=128, window=101, out_dim=128.

__device__ float g_xm  [8u * 1024u * 512u];  // [B, C, T] spatial means (16.8 MB)
__device__ float g_part[8u * 4096u * 128u];  // [ksplit][b*T+t][d] GEMM partials
__device__ float g_y   [4096u * 128u];       // [B*T, 128] normalized projections

#define CP_ASYNC16(dst_u32, src_ptr) \
    asm volatile("cp.async.cg.shared.global [%0], [%1], 16;\n" \
                 :: "r"(dst_u32), "l"(src_ptr))
#define CP_COMMIT() asm volatile("cp.async.commit_group;\n" ::: "memory")
#define CP_WAIT1()  asm volatile("cp.async.wait_group 1;\n" ::: "memory")
#define CP_WAIT0()  asm volatile("cp.async.wait_group 0;\n" ::: "memory")

// Packed fp32x2 FMA (sm_100+): d = a*b + d per 32-bit half. FFMA2 in SASS.
__device__ __forceinline__ void fma2(unsigned long long& d,
                                     unsigned long long a,
                                     unsigned long long b) {
    asm("fma.rn.f32x2 %0, %1, %2, %0;" : "+l"(d) : "l"(a), "l"(b));
}
__device__ __forceinline__ unsigned long long bcast2(float x) {
    unsigned long long r;
    unsigned int u = __float_as_uint(x);
    asm("mov.b64 %0, {%1, %1};" : "=l"(r) : "r"(u));
    return r;
}
__device__ __forceinline__ float lo32(unsigned long long v) {
    return __uint_as_float((unsigned int)(v & 0xffffffffull));
}
__device__ __forceinline__ float hi32(unsigned long long v) {
    return __uint_as_float((unsigned int)(v >> 32));
}

// ---------------------------------------------------------------------------
// Kernel 1: spatial mean over 49 — persistent block, 4 tiles, double-buffered
// cp.async pipeline. Tile = 128 rows = 25088 contiguous floats. While one
// tile is reduced, the next is already streaming in (wait_group 1).
// Stride-49 smem reads are conflict-free (gcd(49,32)=1).
// ---------------------------------------------------------------------------
__global__ void __launch_bounds__(256) k_mean(const float* __restrict__ in) {
    __shared__ __align__(16) float s[2][128 * 49];   // 2 x 25088 B
    int tid = threadIdx.x;
    unsigned int sb[2];
    sb[0] = (unsigned int)__cvta_generic_to_shared(s[0]);
    sb[1] = (unsigned int)__cvta_generic_to_shared(s[1]);
    size_t t0 = (size_t)blockIdx.x * 4;

    auto issue = [&](unsigned int base, size_t tile) {
        const float4* src = (const float4*)in + tile * 1568;
        #pragma unroll
        for (int i = 0; i < 6; i++) {
            int j = tid + i * 256;
            CP_ASYNC16(base + j * 16, src + j);
        }
        int j = tid + 1536;
        if (j < 1568) CP_ASYNC16(base + j * 16, src + j);
        CP_COMMIT();
    };

    issue(sb[0], t0);
    issue(sb[1], t0 + 1);

    #pragma unroll
    for (int i = 0; i < 4; i++) {
        if (i < 3) { CP_WAIT1(); } else { CP_WAIT0(); }
        __syncthreads();
        if (tid < 128) {
            const float* p = s[i & 1] + tid * 49;
            float s0 = 0.f, s1 = 0.f, s2 = 0.f, s3 = 0.f;
            #pragma unroll
            for (int j = 0; j < 48; j += 4) {
                s0 += p[j]; s1 += p[j + 1]; s2 += p[j + 2]; s3 += p[j + 3];
            }
            g_xm[(t0 + i) * 128 + tid] =
                ((s0 + s1) + (s2 + s3) + p[48]) * (1.0f / 49.0f);
        }
        __syncthreads();                 // all reads done before refill
        if (i + 2 < 4) issue(sb[i & 1], t0 + i + 2);
    }
}

// ---------------------------------------------------------------------------
// Kernel 2: projection GEMM, K-split by 8 -> partials, packed f32x2 FMA.
// (unchanged from R7)
// ---------------------------------------------------------------------------
__global__ void __launch_bounds__(256) k_proj(const float* __restrict__ pw) {
    __shared__ __align__(16) float As[16][16];
    __shared__ __align__(16) float Bs[16][128];

    int tid = threadIdx.x;
    int tx  = tid & 31;
    int ty  = tid >> 5;
    int bx  = blockIdx.x;
    int z   = bx & 7;                   // K eighth
    int m0  = (bx >> 3) * 16;           // row tile start
    int b   = m0 >> 9;
    int t0  = m0 & 511;
    const float* Abase = g_xm + (size_t)b * 524288 + t0;
    const float4* pw4 = (const float4*)pw;

    int akk = tid >> 4;
    int amm = tid & 15;

    unsigned long long acc00 = 0ull, acc01 = 0ull;
    unsigned long long acc10 = 0ull, acc11 = 0ull;

    int kbeg = z * 128, kend = kbeg + 128;
    for (int k0 = kbeg; k0 < kend; k0 += 16) {
        As[akk][amm] = Abase[(size_t)(k0 + akk) * 512 + amm];
        {
            int i0 = tid, i1 = tid + 256;
            ((float4*)Bs)[i0] = pw4[(size_t)(k0 + (i0 >> 5)) * 32 + (i0 & 31)];
            ((float4*)Bs)[i1] = pw4[(size_t)(k0 + (i1 >> 5)) * 32 + (i1 & 31)];
        }
        __syncthreads();

        #pragma unroll
        for (int k = 0; k < 16; k++) {
            unsigned long long a0 = bcast2(As[k][ty * 2 + 0]);
            unsigned long long a1 = bcast2(As[k][ty * 2 + 1]);
            const ulonglong2* brow = (const ulonglong2*)Bs[k];
            ulonglong2 bb = brow[tx];
            fma2(acc00, a0, bb.x);
            fma2(acc01, a0, bb.y);
            fma2(acc10, a1, bb.x);
            fma2(acc11, a1, bb.y);
        }
        __syncthreads();
    }

    float4 v0 = make_float4(lo32(acc00), hi32(acc00), lo32(acc01), hi32(acc01));
    float4 v1 = make_float4(lo32(acc10), hi32(acc10), lo32(acc11), hi32(acc11));
    size_t row0 = (size_t)(m0 + ty * 2);
    ((float4*)g_part)[((size_t)z * 4096 + row0)     * 32 + tx] = v0;
    ((float4*)g_part)[((size_t)z * 4096 + row0 + 1) * 32 + tx] = v1;
}

// ---------------------------------------------------------------------------
// Epilogue: sum 8 partials + bias, L2 normalize, write g_y. (unchanged)
// ---------------------------------------------------------------------------
__global__ void __launch_bounds__(256) k_norm(const float* __restrict__ pb) {
    int tid  = threadIdx.x;
    int lane = tid & 31;
    int row  = (blockIdx.x * 256 + tid) >> 5;

    const float4* part4 = (const float4*)g_part;
    float4 v = ((const float4*)pb)[lane];
    #pragma unroll
    for (int z = 0; z < 8; z++) {
        float4 p = part4[((size_t)z * 4096 + row) * 32 + lane];
        v.x += p.x; v.y += p.y; v.z += p.z; v.w += p.w;
    }

    float ss = v.x * v.x + v.y * v.y + v.z * v.z + v.w * v.w;
    #pragma unroll
    for (int o = 16; o; o >>= 1) ss += __shfl_xor_sync(0xffffffffu, ss, o);
    float inv = 1.0f / fmaxf(sqrtf(ss), 1e-12f);
    v.x *= inv; v.y *= inv; v.z *= inv; v.w *= inv;
    ((float4*)g_y)[(size_t)row * 32 + lane] = v;
}

// ---------------------------------------------------------------------------
// Kernel 4: banded cosine-sim + fc + ReLU — shuffle-free smem-tile version.
// Block = 32 t's. Dynamic smem: ys[132 rows][132f] (halo +-50, zero-filled
// outside the batch -> zero-pad semantics for free), bd[32][104], fws[101][128].
// Phase 1: thread = (tloc = tid>>3, wi = tid&7); streams q-row once, FMAs 13
//          independent dot accumulators (w = wi + 8j). Zero shuffles.
// Phase 2: warp = 4 t's, lane = 4 outputs; band scalar = LDS broadcast.
// ---------------------------------------------------------------------------
#define BAND_SMEM_FLOATS (132 * 132 + 32 * 104 + 101 * 128)
#define BAND_SMEM_BYTES  (BAND_SMEM_FLOATS * 4)

__global__ void __launch_bounds__(256) k_band_fc(const float* __restrict__ fw,
                                                 const float* __restrict__ fb,
                                                 float* __restrict__ out) {
    extern __shared__ __align__(16) float dyn[];
    float* ys  = dyn;                        // 132 x 132 (row stride 33 float4)
    float* bd  = dyn + 132 * 132;            // 32 x 104
    float* fws = bd + 32 * 104;              // 101 x 128

    int tid = threadIdx.x;
    int r0  = blockIdx.x * 32;               // first global row of this block
    int lo  = r0 & ~511;                     // batch start
    int hi  = lo + 512;

    const float4* y4   = (const float4*)g_y;
    float4*       ys4  = (float4*)ys;
    const float4* fw4  = (const float4*)fw;
    float4*       fws4 = (float4*)fws;

    // Stage y rows [r0-50, r0+82) with zero fill outside the batch.
    for (int idx = tid; idx < 132 * 32; idx += 256) {
        int rr = idx >> 5, c = idx & 31;
        int gr = r0 - 50 + rr;
        float4 v = make_float4(0.f, 0.f, 0.f, 0.f);
        if (gr >= lo && gr < hi) v = y4[(size_t)gr * 32 + c];
        ys4[rr * 33 + c] = v;
    }
    // Stage fc_w.
    for (int idx = tid; idx < 101 * 32; idx += 256) fws4[idx] = fw4[idx];
    __syncthreads();

    // ---- Phase 1: band dots ----
    {
        int tloc = tid >> 3;                 // 0..31
        int wi   = tid & 7;                  // 0..7
        float acc[13];
        #pragma unroll
        for (int j = 0; j < 13; j++) acc[j] = 0.f;

        const float4* qrow  = ys4 + (50 + tloc) * 33;
        const float4* krow0 = ys4 + tloc * 33;

        #pragma unroll 4
        for (int i = 0; i < 32; i++) {
            float4 q = qrow[i];
            #pragma unroll
            for (int j = 0; j < 13; j++) {
                int w = wi + 8 * j;
                if (w < 101) {
                    float4 k = krow0[w * 33 + i];
                    acc[j] += q.x * k.x + q.y * k.y + q.z * k.z + q.w * k.w;
                }
            }
        }
        #pragma unroll
        for (int j = 0; j < 13; j++) {
            int w = wi + 8 * j;
            if (w < 101) bd[tloc * 104 + w] = acc[j];
        }
    }
    __syncthreads();

    // ---- Phase 2: out[t] = relu(band[t] @ fc_w + fb) ----
    {
        int g    = tid >> 5;                 // warp 0..7 -> t = 4g..4g+3
        int lane = tid & 31;                 // output float4 index
        float4 a0 = make_float4(0.f, 0.f, 0.f, 0.f);
        float4 a1 = a0, a2 = a0, a3 = a0;
        const float* b0p = bd + (4 * g + 0) * 104;
        const float* b1p = bd + (4 * g + 1) * 104;
        const float* b2p = bd + (4 * g + 2) * 104;
        const float* b3p = bd + (4 * g + 3) * 104;

        for (int w = 0; w < 101; w++) {
            float4 f = fws4[w * 32 + lane];
            float s0 = b0p[w], s1 = b1p[w], s2 = b2p[w], s3 = b3p[w];
            a0.x += s0 * f.x; a0.y += s0 * f.y; a0.z += s0 * f.z; a0.w += s0 * f.w;
            a1.x += s1 * f.x; a1.y += s1 * f.y; a1.z += s1 * f.z; a1.w += s1 * f.w;
            a2.x += s2 * f.x; a2.y += s2 * f.y; a2.z += s2 * f.z; a2.w += s2 * f.w;
            a3.x += s3 * f.x; a3.y += s3 * f.y; a3.z += s3 * f.z; a3.w += s3 * f.w;
        }

        float4 bias = ((const float4*)fb)[lane];
        float4* out4 = (float4*)out;
        float4 r;
        r.x = fmaxf(a0.x + bias.x, 0.f); r.y = fmaxf(a0.y + bias.y, 0.f);
        r.z = fmaxf(a0.z + bias.z, 0.f); r.w = fmaxf(a0.w + bias.w, 0.f);
        out4[(size_t)(r0 + 4 * g + 0) * 32 + lane] = r;
        r.x = fmaxf(a1.x + bias.x, 0.f); r.y = fmaxf(a1.y + bias.y, 0.f);
        r.z = fmaxf(a1.z + bias.z, 0.f); r.w = fmaxf(a1.w + bias.w, 0.f);
        out4[(size_t)(r0 + 4 * g + 1) * 32 + lane] = r;
        r.x = fmaxf(a2.x + bias.x, 0.f); r.y = fmaxf(a2.y + bias.y, 0.f);
        r.z = fmaxf(a2.z + bias.z, 0.f); r.w = fmaxf(a2.w + bias.w, 0.f);
        out4[(size_t)(r0 + 4 * g + 2) * 32 + lane] = r;
        r.x = fmaxf(a3.x + bias.x, 0.f); r.y = fmaxf(a3.y + bias.y, 0.f);
        r.z = fmaxf(a3.z + bias.z, 0.f); r.w = fmaxf(a3.w + bias.w, 0.f);
        out4[(size_t)(r0 + 4 * g + 3) * 32 + lane] = r;
    }
}

// ---------------------------------------------------------------------------
extern "C" void kernel_launch(void* const* d_in, const int* in_sizes, int n_in,
                              void* d_out, int out_size) {
    const float* in = (const float*)d_in[0];   // [8,1024,512,7,7]
    const float* pw = (const float*)d_in[1];   // [1024,128]
    const float* pb = (const float*)d_in[2];   // [128]
    const float* fw = (const float*)d_in[3];   // [101,128]
    const float* fb = (const float*)d_in[4];   // [128]
    float* out = (float*)d_out;                // [8,512,128]

    cudaFuncSetAttribute(k_band_fc, cudaFuncAttributeMaxDynamicSharedMemorySize,
                         BAND_SMEM_BYTES);

    k_mean<<<8192, 256>>>(in);                 // 4 tiles/block, double-buffered
    k_proj<<<2048, 256>>>(pw);                 // 256 tiles x 8 K-eighths
    k_norm<<<512, 256>>>(pb);                  // partial sum + bias + L2 norm
    k_band_fc<<<128, 256, BAND_SMEM_BYTES>>>(fw, fb, out);  // 32 t's per block
}